// round 1
// baseline (speedup 1.0000x reference)
#include <cuda_runtime.h>
#include <cuda_bf16.h>
#include <cstdint>

// CPLSTM_20959440405049 — constant-folded solution.
//
// The reference recurrence is degenerate: h0 = 0 and the gate preactivation is
//   g = (h @ a) * (x_t @ b)   (elementwise product),
// so h=0 => g=0 => all gate inputs are exactly 0 =>
//   f=i=o=sigmoid(0)=0.5, g_t=tanh(0)=0 => c' = 0.5*0 + 0.5*0 = 0, h' = 0.5*tanh(0) = 0.
// By induction h_t = c_t = 0 exactly for every step (no rounding on exact zeros).
// Hence:
//   output[s,b,:] = 0 @ dec_w^T + dec_b = dec_b   (exact)
//   c_T = h_T = 0
// The kernel therefore just tiles dec_b over the first S*B*V elements of the
// flattened output and zeros the remainder (the c_T/h_T tails are zeros in any
// flatten order).

__global__ void cplstm_fill_kernel(const float* __restrict__ dec_b,
                                   float* __restrict__ out,
                                   size_t n_total,     // total elements in d_out
                                   size_t n_logits,    // S*B*V elements (dec_b-tiled region)
                                   int V)
{
    const size_t n4 = n_total >> 2;        // number of full float4 chunks
    const size_t nl4 = n_logits >> 2;      // float4 chunks inside the logits region
                                           // (n_logits % 4 == 0 since V % 4 == 0)
    float4* __restrict__ out4 = reinterpret_cast<float4*>(out);

    size_t i = (size_t)blockIdx.x * blockDim.x + threadIdx.x;
    const size_t stride = (size_t)gridDim.x * blockDim.x;

    const float4 zero4 = make_float4(0.f, 0.f, 0.f, 0.f);

    for (; i < n4; i += stride) {
        float4 v;
        if (i < nl4) {
            // element index = 4*i; v-coordinate = (4*i) mod V, always 4-aligned,
            // so the dec_b load is a valid aligned float4 (dec_b is 256B-aligned
            // from the harness allocator).
            size_t e = i << 2;
            int vv = (int)(e % (size_t)V);
            v = *reinterpret_cast<const float4*>(dec_b + vv);
        } else {
            v = zero4;
        }
        // Streaming store: 524 MB output has zero reuse, don't thrash L2.
        __stcs(&out4[i], v);
    }

    // Scalar tail (defensive; n_total is expected to be a multiple of 4).
    if (blockIdx.x == 0 && threadIdx.x == 0) {
        for (size_t e = n4 << 2; e < n_total; ++e) {
            float s = (e < n_logits) ? dec_b[e % (size_t)V] : 0.f;
            __stcs(&out[e], s);
        }
    }
}

extern "C" void kernel_launch(void* const* d_in, const int* in_sizes, int n_in,
                              void* d_out, int out_size)
{
    // metadata order: inp(S,B) int32, emb(V,D), a(H,4R), b(D,4R), ct(4R,H),
    //                 dec_w(V,H), dec_b(V,)
    const float* dec_b = (const float*)d_in[6];

    const size_t SB = (size_t)in_sizes[0];   // S*B = 4096
    const int    V  = in_sizes[6];           // 32000
    const size_t n_total  = (size_t)out_size;
    size_t n_logits = SB * (size_t)V;        // 131,072,000
    if (n_logits > n_total) n_logits = n_total;

    float* out = (float*)d_out;

    // Pure streaming-write kernel: saturate HBM store bandwidth.
    // 148 SMs * 8 blocks * 256 threads, grid-stride (~108 float4 iters/thread).
    const int threads = 256;
    const int blocks  = 148 * 8;
    cplstm_fill_kernel<<<blocks, threads>>>(dec_b, out, n_total, n_logits, V);
}

// round 2
// speedup vs baseline: 1.2242x; 1.2242x over previous
#include <cuda_runtime.h>
#include <cuda_bf16.h>
#include <cstdint>

// CPLSTM_20959440405049 — constant-folded (proof in Round 1: h0=0 + multiplicative
// gate g=(h@a)*(x@b) ==> h_t=c_t=0 exactly for all t; output = dec_b broadcast,
// state outputs = 0). rel_err measured 0.0.
//
// Round 2: restructure the broadcast from "grid-stride + 64-bit mod + reload"
// (issue-bound: alu 29%, DRAM only 64.5%) into a register-resident column-tile
// broadcast: each thread loads its dec_b float4 ONCE, then streams it to its
// column across all assigned rows. Steady state = STG.128.cs + IADD only.

__global__ void cplstm_bcast_kernel(const float4* __restrict__ dec_b4,
                                    float4* __restrict__ out4,
                                    int V4,     // V/4 float4 columns per row
                                    int rows)   // S*B rows
{
    const int col4 = blockIdx.x * blockDim.x + threadIdx.x;
    if (col4 >= V4) return;

    const float4 v = dec_b4[col4];   // one load per thread, L2-resident

    // Row loop: constant stride gridDim.y, address advances by V4*16 bytes
    // (strength-reduced to IADD). Unrolled for outstanding-store MLP.
    float4* __restrict__ p = out4 + (size_t)blockIdx.y * V4 + col4;
    const size_t step = (size_t)gridDim.y * V4;

    int r = blockIdx.y;
    #pragma unroll 4
    for (; r < rows; r += gridDim.y) {
        __stcs(p, v);          // streaming store: 524 MB, zero reuse
        p += step;
    }
}

__global__ void cplstm_zero_tail_kernel(float4* __restrict__ tail4, size_t n4)
{
    size_t i = (size_t)blockIdx.x * blockDim.x + threadIdx.x;
    const size_t stride = (size_t)gridDim.x * blockDim.x;
    const float4 z = make_float4(0.f, 0.f, 0.f, 0.f);
    for (; i < n4; i += stride) __stcs(&tail4[i], z);
}

// Fallback for the (not expected) case V % 4 != 0: Round-1 style generic kernel.
__global__ void cplstm_generic_kernel(const float* __restrict__ dec_b,
                                      float* __restrict__ out,
                                      size_t n_total, size_t n_logits, int V)
{
    size_t i = (size_t)blockIdx.x * blockDim.x + threadIdx.x;
    const size_t stride = (size_t)gridDim.x * blockDim.x;
    for (; i < n_total; i += stride) {
        float s = (i < n_logits) ? dec_b[i % (size_t)V] : 0.f;
        __stcs(&out[i], s);
    }
}

extern "C" void kernel_launch(void* const* d_in, const int* in_sizes, int n_in,
                              void* d_out, int out_size)
{
    // metadata order: inp(S,B) int32, emb(V,D), a(H,4R), b(D,4R), ct(4R,H),
    //                 dec_w(V,H), dec_b(V,)
    const float* dec_b = (const float*)d_in[6];
    float*       out   = (float*)d_out;

    const size_t SB = (size_t)in_sizes[0];   // S*B = 4096 rows
    const int    V  = in_sizes[6];           // 32000
    const size_t n_total = (size_t)out_size;
    size_t n_logits = SB * (size_t)V;
    if (n_logits > n_total) n_logits = n_total;

    if ((V & 3) != 0 || (n_logits != SB * (size_t)V)) {
        // defensive generic path (never taken for this problem's shapes)
        cplstm_generic_kernel<<<148 * 8, 256>>>(dec_b, out, n_total, n_logits, V);
        return;
    }

    const int V4   = V >> 2;                 // 8000 float4 per row
    const int rows = (int)SB;                // 4096

    // Grid: X tiles columns (32 blocks x 256 threads covers 8192 >= 8000 float4),
    // Y tiles rows. gridDim.y=128 -> 4096 blocks total (~3.5 waves at 8 CTA/SM),
    // 32 pure stores per thread.
    dim3 block(256, 1, 1);
    dim3 grid((V4 + 255) / 256, 128, 1);
    cplstm_bcast_kernel<<<grid, block>>>(
        (const float4*)dec_b, (float4*)out, V4, rows);

    // Zero the (c_T, h_T) tail: 2*B*H floats = 256 KB. Trivial second launch.
    const size_t n_tail = n_total - n_logits;
    if (n_tail > 0) {
        float* tail = out + n_logits;
        if ((n_tail & 3) == 0 && ((n_logits & 3) == 0)) {
            const size_t n4 = n_tail >> 2;
            int blks = (int)((n4 + 255) / 256);
            if (blks > 256) blks = 256;
            cplstm_zero_tail_kernel<<<blks, 256>>>((float4*)tail, n4);
        } else {
            cplstm_generic_kernel<<<64, 256>>>(dec_b, tail, n_tail, 0, V);
        }
    }
}